// round 11
// baseline (speedup 1.0000x reference)
#include <cuda_runtime.h>
#include <cstdint>
#include <cstddef>

constexpr int B_  = 4;
constexpr int DE  = 128;
constexpr int DO  = 512;
constexpr int K_  = 12960;   // 8*30*54
constexpr int Q_  = 1620;    // 30*54

constexpr int QT   = 96;
constexpr int NQT  = 17;          // ceil(1620/96)
constexpr int QPAD = NQT * QT;    // 1632
constexpr int KT   = 128;
constexpr int NKT  = 102;         // ceil(12960/128)

constexpr int MEM_ELEMS = B_ * DO * Q_;
constexpr float SCALE = 0.088388347648318447f;  // 1/sqrt(128)

// scratch: static device globals (no runtime allocation)
// g_e padded: K3's cp.async tail chunks may read up to 48B past the last row.
__device__ float g_e[(size_t)B_ * K_ * Q_ + 64];
__device__ float g_mo[(size_t)B_ * DO * K_];          // tf32-pre-rounded m_out
__device__ float g_part[(size_t)B_ * NKT * QPAD];
__device__ float g_inv[(size_t)B_ * QPAD];

__device__ __forceinline__ uint32_t f2tf(float x) {
    uint32_t u;
    asm("cvt.rna.tf32.f32 %0, %1;" : "=r"(u) : "f"(x));
    return u;
}

// D(16x8) += A(16x8 row) * B(8x8 col), tf32 in, fp32 accum
__device__ __forceinline__ void mma8(float* c, const uint32_t* a, const uint32_t* b) {
    asm volatile(
        "mma.sync.aligned.m16n8k8.row.col.f32.tf32.tf32.f32 "
        "{%0,%1,%2,%3}, {%4,%5,%6,%7}, {%8,%9}, {%0,%1,%2,%3};\n"
        : "+f"(c[0]), "+f"(c[1]), "+f"(c[2]), "+f"(c[3])
        : "r"(a[0]), "r"(a[1]), "r"(a[2]), "r"(a[3]),
          "r"(b[0]), "r"(b[1]));
}

__device__ __forceinline__ uint32_t s2u(const void* p) {
    return (uint32_t)__cvta_generic_to_shared(p);
}
__device__ __forceinline__ void cpa16(uint32_t dst, const float* src) {
    asm volatile("cp.async.cg.shared.global [%0], [%1], 16;\n" :: "r"(dst), "l"(src));
}
__device__ __forceinline__ void cpcommit() {
    asm volatile("cp.async.commit_group;\n");
}

// ===========================================================================
// K0: pre-round m_out to tf32 (so K3's cp.async path needs no conversion)
// ===========================================================================
__global__ void k0_round(const float* __restrict__ src)
{
    size_t i = ((size_t)blockIdx.x * 256 + threadIdx.x) * 4;
    float4 v = *reinterpret_cast<const float4*>(src + i);
    v.x = __uint_as_float(f2tf(v.x));
    v.y = __uint_as_float(f2tf(v.y));
    v.z = __uint_as_float(f2tf(v.z));
    v.w = __uint_as_float(f2tf(v.w));
    *reinterpret_cast<float4*>(g_mo + i) = v;
}

// ===========================================================================
// K1: e = exp(S/sqrt(DE)); S = m_in^T q_in. Column partial sums to g_part.
// g_e stored tf32-ROUNDED so K3 consumes raw bits exactly.
// Double-buffered smem over the 4 d-chunks; one barrier per chunk:
//   iter dc:  mma(buf dc&1)  ->  load(dc+1 into buf ~)  ->  sync
// ===========================================================================
constexpr int K1_ASZ = 128 * 36;   // u32 per A buffer
constexpr int K1_BSZ = 96 * 36;    // u32 per B buffer
constexpr int K1_SMEMB = (2 * K1_ASZ + 2 * K1_BSZ + 384) * 4;   // 66048 B

__global__ __launch_bounds__(256, 2)
void k1_scores(const float* __restrict__ m_in, const float* __restrict__ q_in)
{
    extern __shared__ uint32_t s1[];
    uint32_t* As = s1;                          // 2 buffers
    uint32_t* Bs = s1 + 2 * K1_ASZ;             // 2 buffers
    float*    cs = (float*)(s1 + 2 * K1_ASZ + 2 * K1_BSZ);   // 384 floats

    const int tid  = threadIdx.x;
    const int wid  = tid >> 5;
    const int lane = tid & 31;
    const int g    = lane >> 2;
    const int tg   = lane & 3;
    const int wm   = wid & 3;
    const int wn   = wid >> 2;

    const int kt = blockIdx.x;
    const int qt = blockIdx.y;
    const int b  = blockIdx.z;
    const int k0 = kt * KT;
    const int q0 = qt * QT;

    const float* mi = m_in + (size_t)b * DE * K_;
    const float* qi = q_in + (size_t)b * DE * Q_;

    float acc[2][6][4];
#pragma unroll
    for (int mt = 0; mt < 2; ++mt)
#pragma unroll
        for (int nt = 0; nt < 6; ++nt)
#pragma unroll
            for (int j = 0; j < 4; ++j) acc[mt][nt][j] = 0.f;

    auto load_tiles = [&](int dc, int buf) {
        uint32_t* A  = As + buf * K1_ASZ;
        uint32_t* Bb = Bs + buf * K1_BSZ;
#pragma unroll
        for (int it = 0; it < 16; ++it) {                  // A: 128k x 32d
            int i  = tid + it * 256;
            int kk = i & 127;
            int dd = i >> 7;
            int kg = k0 + kk;
            float v = (kg < K_) ? mi[(size_t)(dc * 32 + dd) * K_ + kg] : 0.f;
            A[kk * 36 + dd] = f2tf(v);
        }
#pragma unroll
        for (int it = 0; it < 12; ++it) {                  // B: 96q x 32d
            int i  = tid + it * 256;
            int q  = i % 96;
            int dd = i / 96;
            int qg = q0 + q;
            float v = (qg < Q_) ? qi[(size_t)(dc * 32 + dd) * Q_ + qg] : 0.f;
            Bb[q * 36 + dd] = f2tf(v);
        }
    };

    load_tiles(0, 0);
    __syncthreads();

#pragma unroll
    for (int dc = 0; dc < 4; ++dc) {
        const uint32_t* A  = As + (dc & 1) * K1_ASZ;
        const uint32_t* Bb = Bs + (dc & 1) * K1_BSZ;

#pragma unroll
        for (int ks = 0; ks < 4; ++ks) {
            const int c = ks * 8 + tg;
            uint32_t af[2][4];
#pragma unroll
            for (int mt = 0; mt < 2; ++mt) {
                int r = wm * 32 + mt * 16 + g;
                af[mt][0] = A[r * 36 + c];
                af[mt][1] = A[(r + 8) * 36 + c];
                af[mt][2] = A[r * 36 + c + 4];
                af[mt][3] = A[(r + 8) * 36 + c + 4];
            }
#pragma unroll
            for (int nt = 0; nt < 6; ++nt) {
                int n = wn * 48 + nt * 8 + g;
                uint32_t bf[2] = { Bb[n * 36 + c], Bb[n * 36 + c + 4] };
                mma8(acc[0][nt], af[0], bf);
                mma8(acc[1][nt], af[1], bf);
            }
        }
        if (dc < 3) load_tiles(dc + 1, (dc + 1) & 1);
        __syncthreads();
    }

    // exp + masked column sums
    float ls[6][2];
#pragma unroll
    for (int nt = 0; nt < 6; ++nt) { ls[nt][0] = 0.f; ls[nt][1] = 0.f; }

#pragma unroll
    for (int mt = 0; mt < 2; ++mt)
#pragma unroll
        for (int nt = 0; nt < 6; ++nt)
#pragma unroll
            for (int j = 0; j < 4; ++j) {
                int r  = wm * 32 + mt * 16 + ((j & 2) ? (g + 8) : g);
                int kg = k0 + r;
                float e = (kg < K_) ? __expf(acc[mt][nt][j] * SCALE) : 0.f;
                acc[mt][nt][j] = e;
                ls[nt][j & 1] += e;
            }

#pragma unroll
    for (int nt = 0; nt < 6; ++nt)
#pragma unroll
        for (int p = 0; p < 2; ++p) {
            float v = ls[nt][p];
            v += __shfl_xor_sync(0xffffffffu, v, 4);
            v += __shfl_xor_sync(0xffffffffu, v, 8);
            v += __shfl_xor_sync(0xffffffffu, v, 16);
            if (g == 0) cs[wm * 96 + wn * 48 + nt * 8 + tg * 2 + p] = v;
        }
    __syncthreads();

    if (tid < 96) {
        float s = cs[tid] + cs[96 + tid] + cs[192 + tid] + cs[288 + tid];
        g_part[((size_t)b * NKT + kt) * QPAD + qt * QT + tid] = s;
    }

    // stage e through smem for coalesced g_e stores (tf32-rounded)
    float* stg = reinterpret_cast<float*>(As);
#pragma unroll 1
    for (int chunk = 0; chunk < 4; ++chunk) {
        __syncthreads();
        if (wm == chunk) {
#pragma unroll
            for (int mt = 0; mt < 2; ++mt)
#pragma unroll
                for (int nt = 0; nt < 6; ++nt)
#pragma unroll
                    for (int j = 0; j < 4; ++j) {
                        int r = mt * 16 + ((j & 2) ? (g + 8) : g);
                        int c = wn * 48 + nt * 8 + tg * 2 + (j & 1);
                        stg[r * 100 + c] = __uint_as_float(f2tf(acc[mt][nt][j]));
                    }
        }
        __syncthreads();
        for (int i = tid; i < 32 * 96; i += 256) {
            int r = i / 96, c = i - r * 96;
            int kg = k0 + chunk * 32 + r;
            int qg = q0 + c;
            if (kg < K_ && qg < Q_)
                g_e[((size_t)b * K_ + kg) * Q_ + qg] = stg[r * 100 + c];
        }
    }
}

// ===========================================================================
// K2: g_inv[b,q] = 1 / (exp(const) + sum_kt g_part)
// ===========================================================================
__global__ void k2_inv(const float* __restrict__ cst)
{
    int t = blockIdx.x * blockDim.x + threadIdx.x;
    if (t >= B_ * QPAD) return;
    int b  = t / QPAD;
    int qp = t - b * QPAD;
    float d = expf(cst[0]);
    const float* gp = g_part + (size_t)b * NKT * QPAD + qp;
#pragma unroll 4
    for (int kt = 0; kt < NKT; ++kt) d += gp[(size_t)kt * QPAD];
    g_inv[t] = 1.f / d;
}

// ===========================================================================
// K3: U = g_mo @ g_e, 3-stage cp.async pipeline, ONE barrier per k-iter.
//     mem = U*inv[q] in epilogue; p = g_e*inv streamed from smem B tile
//     (1/4 duty cycle per dot-block), issued BEFORE the mma block.
// Buffer safety: loads at iter kc target stage (kc+2)%3 == stage read at
// iter kc-1; every warp has passed iter kc's barrier only after finishing
// iter kc-1's reads, so the single barrier protects the overwrite.
// ===========================================================================
constexpr int ASTR  = 128 * 36;   // floats per A stage (stride 36: CF frag loads)
constexpr int BSTR  = 32 * 104;   // floats per B stage (stride 104: CF)
constexpr int ASZB  = ASTR * 4;
constexpr int BSZB  = BSTR * 4;
constexpr int SMEMF3 = 3 * ASTR + 3 * BSTR + 96;   // 23904 floats = 95616 B

__global__ __launch_bounds__(256, 2)
void k3_out(float* __restrict__ out_mem, float* __restrict__ out_p)
{
    extern __shared__ float sm[];
    float* Ab   = sm;                       // 3 stages
    float* Bb   = sm + 3 * ASTR;            // 3 stages
    float* sinv = sm + 3 * ASTR + 3 * BSTR;

    const int tid  = threadIdx.x;
    const int wid  = tid >> 5;
    const int lane = tid & 31;
    const int g    = lane >> 2;
    const int tg   = lane & 3;
    const int wm   = wid & 3;
    const int wn   = wid >> 2;

    const int dot = blockIdx.x;   // 0..3
    const int qt  = blockIdx.y;   // 0..16
    const int b   = blockIdx.z;
    const int q0  = qt * QT;
    const int do0 = dot * 128;

    if (tid < 96) sinv[tid] = g_inv[(size_t)b * QPAD + q0 + tid];

    // per-thread cp.async descriptors (offsets fixed; pointers advance by stage)
    const float* asrc[4]; uint32_t aoff[4];
#pragma unroll
    for (int it = 0; it < 4; ++it) {
        int i = tid + it * 256;          // A: 128 rows x 32 floats = 1024 x 16B
        int row = i >> 3;
        int kc4 = (i & 7) * 4;
        asrc[it] = g_mo + ((size_t)b * DO + do0 + row) * K_ + kc4;
        aoff[it] = (uint32_t)((row * 36 + kc4) * 4);
    }
    const float* bsrc[3]; uint32_t boff[3]; int bkk[3], bqc[3];
#pragma unroll
    for (int it = 0; it < 3; ++it) {
        int i = tid + it * 256;          // B: 32 rows x 96 floats = 768 x 16B
        int kk = i / 24;
        int qc = (i - kk * 24) * 4;
        bkk[it] = kk; bqc[it] = qc;
        bsrc[it] = g_e + (size_t)b * K_ * Q_ + (size_t)kk * Q_ + q0 + qc;
        boff[it] = (uint32_t)((kk * 104 + qc) * 4);
    }
    const uint32_t Abase = s2u(Ab);
    const uint32_t Bbase = s2u(Bb);

    float acc[2][6][4];
#pragma unroll
    for (int mt = 0; mt < 2; ++mt)
#pragma unroll
        for (int nt = 0; nt < 6; ++nt)
#pragma unroll
            for (int j = 0; j < 4; ++j) acc[mt][nt][j] = 0.f;

    // prologue: stage 0 and stage 1
#pragma unroll
    for (int s = 0; s < 2; ++s) {
        const uint32_t sa = Abase + s * ASZB;
        const uint32_t sb = Bbase + s * BSZB;
#pragma unroll
        for (int it = 0; it < 4; ++it) { cpa16(sa + aoff[it], asrc[it]); asrc[it] += 32; }
#pragma unroll
        for (int it = 0; it < 3; ++it) { cpa16(sb + boff[it], bsrc[it]); bsrc[it] += (size_t)32 * Q_; }
        cpcommit();
    }

    float* pout = out_p + (size_t)b * K_ * Q_;

    int rd = 0, wr = 2;
#pragma unroll 1
    for (int kc = 0; kc < 405; ++kc) {
        if (kc < 404) asm volatile("cp.async.wait_group 1;\n" ::: "memory");
        else          asm volatile("cp.async.wait_group 0;\n" ::: "memory");
        __syncthreads();   // single barrier per iteration

        if (kc <= 402) {   // issue stage kc+2
            const uint32_t sa = Abase + wr * ASZB;
            const uint32_t sb = Bbase + wr * BSZB;
#pragma unroll
            for (int it = 0; it < 4; ++it) { cpa16(sa + aoff[it], asrc[it]); asrc[it] += 32; }
#pragma unroll
            for (int it = 0; it < 3; ++it) { cpa16(sb + boff[it], bsrc[it]); bsrc[it] += (size_t)32 * Q_; }
            cpcommit();
        }

        const float* A  = Ab + rd * ASTR;
        const float* Bv = Bb + rd * BSTR;

        // p output first: STGs drain under the mma block below
        if ((kc & 3) == dot) {
            const int k0 = kc * 32;
#pragma unroll
            for (int it = 0; it < 3; ++it) {
                const int kk = bkk[it], qc = bqc[it];
                float4 v = *reinterpret_cast<const float4*>(Bv + kk * 104 + qc);
                float4 w;
                w.x = v.x * sinv[qc];
                w.y = v.y * sinv[qc + 1];
                w.z = v.z * sinv[qc + 2];
                w.w = v.w * sinv[qc + 3];
                const int qg = q0 + qc;
                float* dst = pout + (size_t)(k0 + kk) * Q_ + qg;
                if (qg + 3 < Q_) {
                    *reinterpret_cast<float4*>(dst) = w;
                } else {
                    if (qg     < Q_) dst[0] = w.x;
                    if (qg + 1 < Q_) dst[1] = w.y;
                    if (qg + 2 < Q_) dst[2] = w.z;
                    if (qg + 3 < Q_) dst[3] = w.w;
                }
            }
        }

#pragma unroll
        for (int ks = 0; ks < 4; ++ks) {
            const int c = ks * 8 + tg;
            uint32_t af[2][4];
#pragma unroll
            for (int mt = 0; mt < 2; ++mt) {
                int r = wm * 32 + mt * 16 + g;
                af[mt][0] = __float_as_uint(A[r * 36 + c]);
                af[mt][1] = __float_as_uint(A[(r + 8) * 36 + c]);
                af[mt][2] = __float_as_uint(A[r * 36 + c + 4]);
                af[mt][3] = __float_as_uint(A[(r + 8) * 36 + c + 4]);
            }
#pragma unroll
            for (int nt = 0; nt < 6; ++nt) {
                int n = wn * 48 + nt * 8 + g;
                uint32_t bf[2] = { __float_as_uint(Bv[c * 104 + n]),
                                   __float_as_uint(Bv[(c + 4) * 104 + n]) };
                mma8(acc[0][nt], af[0], bf);
                mma8(acc[1][nt], af[1], bf);
            }
        }

        rd = (rd == 2) ? 0 : rd + 1;
        wr = (wr == 2) ? 0 : wr + 1;
    }

    // epilogue: mem = U * inv[q]
#pragma unroll
    for (int mt = 0; mt < 2; ++mt)
#pragma unroll
        for (int nt = 0; nt < 6; ++nt)
#pragma unroll
            for (int j = 0; j < 4; ++j) {
                int r  = wm * 32 + mt * 16 + ((j & 2) ? (g + 8) : g);
                int cq = wn * 48 + nt * 8 + tg * 2 + (j & 1);
                int qg = q0 + cq;
                if (qg < Q_)
                    out_mem[((size_t)b * DO + do0 + r) * Q_ + qg] =
                        acc[mt][nt][j] * sinv[cq];
            }
}

extern "C" void kernel_launch(void* const* d_in, const int* in_sizes, int n_in,
                              void* d_out, int out_size) {
    const float* m_in  = (const float*)d_in[0];
    const float* m_out = (const float*)d_in[1];
    const float* q_in  = (const float*)d_in[2];
    const float* cst   = (const float*)d_in[3];
    float* out = (float*)d_out;

    cudaFuncSetAttribute(k1_scores, cudaFuncAttributeMaxDynamicSharedMemorySize,
                         K1_SMEMB);
    cudaFuncSetAttribute(k3_out, cudaFuncAttributeMaxDynamicSharedMemorySize,
                         SMEMF3 * 4);

    k0_round<<<(B_ * DO * K_) / (4 * 256), 256>>>(m_out);   // exact division
    k1_scores<<<dim3(NKT, NQT, B_), 256, K1_SMEMB>>>(m_in, q_in);
    k2_inv<<<(B_ * QPAD + 255) / 256, 256>>>(cst);
    k3_out<<<dim3(4, NQT, B_), 256, SMEMF3 * 4>>>(out, out + MEM_ELEMS);
}

// round 12
// speedup vs baseline: 1.3133x; 1.3133x over previous
#include <cuda_runtime.h>
#include <cstdint>
#include <cstddef>

constexpr int B_  = 4;
constexpr int DE  = 128;
constexpr int DO  = 512;
constexpr int K_  = 12960;   // 8*30*54
constexpr int Q_  = 1620;    // 30*54

constexpr int QT   = 96;
constexpr int NQT  = 17;          // ceil(1620/96)
constexpr int QPAD = NQT * QT;    // 1632
constexpr int KT   = 128;
constexpr int NKT  = 102;         // ceil(12960/128)

constexpr int MEM_ELEMS = B_ * DO * Q_;
constexpr float SCALE = 0.088388347648318447f;  // 1/sqrt(128)

// scratch: static device globals (no runtime allocation)
// g_e padded: K3's cp.async tail chunks may read up to 48B past the last row.
__device__ float g_e[(size_t)B_ * K_ * Q_ + 64];
__device__ float g_mo[(size_t)B_ * DO * K_];   // tf32-rounded, k-interleaved m_out
__device__ float g_part[(size_t)B_ * NKT * QPAD];
__device__ float g_inv[(size_t)B_ * QPAD];

__device__ __forceinline__ uint32_t f2tf(float x) {
    uint32_t u;
    asm("cvt.rna.tf32.f32 %0, %1;" : "=r"(u) : "f"(x));
    return u;
}

// D(16x8) += A(16x8 row) * B(8x8 col), tf32 in, fp32 accum
__device__ __forceinline__ void mma8(float* c, const uint32_t* a, const uint32_t* b) {
    asm volatile(
        "mma.sync.aligned.m16n8k8.row.col.f32.tf32.tf32.f32 "
        "{%0,%1,%2,%3}, {%4,%5,%6,%7}, {%8,%9}, {%0,%1,%2,%3};\n"
        : "+f"(c[0]), "+f"(c[1]), "+f"(c[2]), "+f"(c[3])
        : "r"(a[0]), "r"(a[1]), "r"(a[2]), "r"(a[3]),
          "r"(b[0]), "r"(b[1]));
}

__device__ __forceinline__ uint32_t s2u(const void* p) {
    return (uint32_t)__cvta_generic_to_shared(p);
}
__device__ __forceinline__ void cpa16(uint32_t dst, const float* src) {
    asm volatile("cp.async.cg.shared.global [%0], [%1], 16;\n" :: "r"(dst), "l"(src));
}
__device__ __forceinline__ void cpcommit() {
    asm volatile("cp.async.commit_group;\n");
}

// ===========================================================================
// K0: tf32-round m_out AND k-interleave each 32-wide k-chunk:
//     dest word c' in [0,32) holds source c = 8*(c'%4) + c'/4.
//     (So K3's per-thread A-frags across the 4 mma k-steps are one float4.)
// ===========================================================================
__global__ void k0_round(const float* __restrict__ src)
{
    size_t f = (size_t)blockIdx.x * 256 + threadIdx.x;   // float4 index
    size_t w = f * 4;                                    // word base (c' = 4j)
    size_t base32 = (w >> 5) << 5;                       // 32-word block start
    int    j      = (int)((w >> 2) & 7);                 // chunk index 0..7
    float4 v;
    v.x = __uint_as_float(f2tf(src[base32 + j]));        // s=0: c = j
    v.y = __uint_as_float(f2tf(src[base32 + 8 + j]));    // s=1: c = 8+j
    v.z = __uint_as_float(f2tf(src[base32 + 16 + j]));   // s=2
    v.w = __uint_as_float(f2tf(src[base32 + 24 + j]));   // s=3
    *reinterpret_cast<float4*>(g_mo + w) = v;
}

// ===========================================================================
// K1 (R10-proven form): e = exp(S/sqrt(DE)); S = m_in^T q_in.
// Column partial sums to g_part. g_e stored tf32-ROUNDED.
// ===========================================================================
__global__ __launch_bounds__(256, 2)
void k1_scores(const float* __restrict__ m_in, const float* __restrict__ q_in)
{
    __shared__ uint32_t As[128 * 36];
    __shared__ uint32_t Bs[96 * 36];
    __shared__ float    cs[4 * 96];

    const int tid  = threadIdx.x;
    const int wid  = tid >> 5;
    const int lane = tid & 31;
    const int g    = lane >> 2;
    const int tg   = lane & 3;
    const int wm   = wid & 3;
    const int wn   = wid >> 2;

    const int kt = blockIdx.x;
    const int qt = blockIdx.y;
    const int b  = blockIdx.z;
    const int k0 = kt * KT;
    const int q0 = qt * QT;

    const float* mi = m_in + (size_t)b * DE * K_;
    const float* qi = q_in + (size_t)b * DE * Q_;

    float acc[2][6][4];
#pragma unroll
    for (int mt = 0; mt < 2; ++mt)
#pragma unroll
        for (int nt = 0; nt < 6; ++nt)
#pragma unroll
            for (int j = 0; j < 4; ++j) acc[mt][nt][j] = 0.f;

    for (int dc = 0; dc < 4; ++dc) {
#pragma unroll
        for (int it = 0; it < 16; ++it) {
            int i  = tid + it * 256;
            int kk = i & 127;
            int dd = i >> 7;
            int kg = k0 + kk;
            float v = (kg < K_) ? mi[(size_t)(dc * 32 + dd) * K_ + kg] : 0.f;
            As[kk * 36 + dd] = f2tf(v);
        }
#pragma unroll
        for (int it = 0; it < 12; ++it) {
            int i  = tid + it * 256;
            int q  = i % 96;
            int dd = i / 96;
            int qg = q0 + q;
            float v = (qg < Q_) ? qi[(size_t)(dc * 32 + dd) * Q_ + qg] : 0.f;
            Bs[q * 36 + dd] = f2tf(v);
        }
        __syncthreads();

#pragma unroll
        for (int ks = 0; ks < 4; ++ks) {
            const int c = ks * 8 + tg;
            uint32_t af[2][4];
#pragma unroll
            for (int mt = 0; mt < 2; ++mt) {
                int r = wm * 32 + mt * 16 + g;
                af[mt][0] = As[r * 36 + c];
                af[mt][1] = As[(r + 8) * 36 + c];
                af[mt][2] = As[r * 36 + c + 4];
                af[mt][3] = As[(r + 8) * 36 + c + 4];
            }
#pragma unroll
            for (int nt = 0; nt < 6; ++nt) {
                int n = wn * 48 + nt * 8 + g;
                uint32_t bf[2] = { Bs[n * 36 + c], Bs[n * 36 + c + 4] };
                mma8(acc[0][nt], af[0], bf);
                mma8(acc[1][nt], af[1], bf);
            }
        }
        __syncthreads();
    }

    float ls[6][2];
#pragma unroll
    for (int nt = 0; nt < 6; ++nt) { ls[nt][0] = 0.f; ls[nt][1] = 0.f; }

#pragma unroll
    for (int mt = 0; mt < 2; ++mt)
#pragma unroll
        for (int nt = 0; nt < 6; ++nt)
#pragma unroll
            for (int j = 0; j < 4; ++j) {
                int r  = wm * 32 + mt * 16 + ((j & 2) ? (g + 8) : g);
                int kg = k0 + r;
                float e = (kg < K_) ? __expf(acc[mt][nt][j] * SCALE) : 0.f;
                acc[mt][nt][j] = e;
                ls[nt][j & 1] += e;
            }

#pragma unroll
    for (int nt = 0; nt < 6; ++nt)
#pragma unroll
        for (int p = 0; p < 2; ++p) {
            float v = ls[nt][p];
            v += __shfl_xor_sync(0xffffffffu, v, 4);
            v += __shfl_xor_sync(0xffffffffu, v, 8);
            v += __shfl_xor_sync(0xffffffffu, v, 16);
            if (g == 0) cs[wm * 96 + wn * 48 + nt * 8 + tg * 2 + p] = v;
        }
    __syncthreads();

    if (tid < 96) {
        float s = cs[tid] + cs[96 + tid] + cs[192 + tid] + cs[288 + tid];
        g_part[((size_t)b * NKT + kt) * QPAD + qt * QT + tid] = s;
    }

    float* stg = reinterpret_cast<float*>(As);
#pragma unroll 1
    for (int chunk = 0; chunk < 4; ++chunk) {
        __syncthreads();
        if (wm == chunk) {
#pragma unroll
            for (int mt = 0; mt < 2; ++mt)
#pragma unroll
                for (int nt = 0; nt < 6; ++nt)
#pragma unroll
                    for (int j = 0; j < 4; ++j) {
                        int r = mt * 16 + ((j & 2) ? (g + 8) : g);
                        int c = wn * 48 + nt * 8 + tg * 2 + (j & 1);
                        stg[r * 100 + c] = __uint_as_float(f2tf(acc[mt][nt][j]));
                    }
        }
        __syncthreads();
        for (int i = tid; i < 32 * 96; i += 256) {
            int r = i / 96, c = i - r * 96;
            int kg = k0 + chunk * 32 + r;
            int qg = q0 + c;
            if (kg < K_ && qg < Q_)
                g_e[((size_t)b * K_ + kg) * Q_ + qg] = stg[r * 100 + c];
        }
    }
}

// ===========================================================================
// K2: g_inv[b,q] = 1 / (exp(const) + sum_kt g_part)
// ===========================================================================
__global__ void k2_inv(const float* __restrict__ cst)
{
    int t = blockIdx.x * blockDim.x + threadIdx.x;
    if (t >= B_ * QPAD) return;
    int b  = t / QPAD;
    int qp = t - b * QPAD;
    float d = expf(cst[0]);
    const float* gp = g_part + (size_t)b * NKT * QPAD + qp;
#pragma unroll 4
    for (int kt = 0; kt < NKT; ++kt) d += gp[(size_t)kt * QPAD];
    g_inv[t] = 1.f / d;
}

// ===========================================================================
// K3: U = g_mo @ g_e, 2-stage cp.async pipeline (R10-proven control flow),
//     vectorized fragment loads:
//       A: k-interleaved layout (stride 48) -> 8 LDS.128/warp/iter (all ks)
//       B: column remap sigma(nt,j)=6j+nt   -> 24 LDS.64/warp/iter
//     mem = U*inv[q] epilogue; p = g_e*inv from smem B tile (1/4 duty).
// ===========================================================================
constexpr int ASTR  = 128 * 48;   // floats per A stage (stride 48: CF LDS.128)
constexpr int BSTR  = 32 * 104;   // floats per B stage (stride 104: CF LDS.64)
constexpr int SMEMF = 2 * ASTR + 2 * BSTR + 96;   // 19040 floats = 76160 B

__global__ __launch_bounds__(256, 2)
void k3_out(float* __restrict__ out_mem, float* __restrict__ out_p)
{
    extern __shared__ float sm[];
    float* Ab   = sm;
    float* Bb   = sm + 2 * ASTR;
    float* sinv = sm + 2 * ASTR + 2 * BSTR;

    const int tid  = threadIdx.x;
    const int wid  = tid >> 5;
    const int lane = tid & 31;
    const int g    = lane >> 2;
    const int tg   = lane & 3;
    const int wm   = wid & 3;
    const int wn   = wid >> 2;

    const int dot = blockIdx.x;   // 0..3
    const int qt  = blockIdx.y;   // 0..16
    const int b   = blockIdx.z;
    const int q0  = qt * QT;
    const int do0 = dot * 128;

    if (tid < 96) sinv[tid] = g_inv[(size_t)b * QPAD + q0 + tid];

    // per-thread cp.async descriptors
    const float* asrc[4]; uint32_t aoff[4];
#pragma unroll
    for (int it = 0; it < 4; ++it) {
        int i   = tid + it * 256;        // A: 128 rows x 8 chunks = 1024 x 16B
        int row = i >> 3;
        int j   = i & 7;                 // interleaved chunk (dest col 4j)
        asrc[it] = g_mo + ((size_t)b * DO + do0 + row) * K_ + j * 4;
        aoff[it] = (uint32_t)((row * 48 + j * 4) * 4);
    }
    const float* bsrc[3]; uint32_t boff[3]; int bkk[3], bqc[3];
#pragma unroll
    for (int it = 0; it < 3; ++it) {
        int i  = tid + it * 256;         // B: 32 rows x 96 floats = 768 x 16B
        int kk = i / 24;
        int qc = (i - kk * 24) * 4;
        bkk[it] = kk; bqc[it] = qc;
        bsrc[it] = g_e + (size_t)b * K_ * Q_ + (size_t)kk * Q_ + q0 + qc;
        boff[it] = (uint32_t)((kk * 104 + qc) * 4);
    }
    const uint32_t Abase = s2u(Ab);
    const uint32_t Bbase = s2u(Bb);

    float acc[2][6][4];
#pragma unroll
    for (int mt = 0; mt < 2; ++mt)
#pragma unroll
        for (int nt = 0; nt < 6; ++nt)
#pragma unroll
            for (int j = 0; j < 4; ++j) acc[mt][nt][j] = 0.f;

    // prologue: stage kc=0 into buffer 0
#pragma unroll
    for (int it = 0; it < 4; ++it) cpa16(Abase + aoff[it], asrc[it]);
#pragma unroll
    for (int it = 0; it < 3; ++it) cpa16(Bbase + boff[it], bsrc[it]);
    cpcommit();
#pragma unroll
    for (int it = 0; it < 4; ++it) asrc[it] += 32;
#pragma unroll
    for (int it = 0; it < 3; ++it) bsrc[it] += (size_t)32 * Q_;

    float* pout = out_p + (size_t)b * K_ * Q_;

#pragma unroll 1
    for (int kc = 0; kc < 405; ++kc) {
        if (kc < 404) {
            const uint32_t sa = Abase + ((kc + 1) & 1) * (ASTR * 4);
            const uint32_t sb = Bbase + ((kc + 1) & 1) * (BSTR * 4);
#pragma unroll
            for (int it = 0; it < 4; ++it) { cpa16(sa + aoff[it], asrc[it]); asrc[it] += 32; }
#pragma unroll
            for (int it = 0; it < 3; ++it) { cpa16(sb + boff[it], bsrc[it]); bsrc[it] += (size_t)32 * Q_; }
            cpcommit();
            asm volatile("cp.async.wait_group 1;\n" ::: "memory");
        } else {
            asm volatile("cp.async.wait_group 0;\n" ::: "memory");
        }
        __syncthreads();

        const float* A  = Ab + (kc & 1) * ASTR;
        const float* Bv = Bb + (kc & 1) * BSTR;

        // A-frags for ALL 4 ks: 8 conflict-free LDS.128
        float4 afv[2][4];
#pragma unroll
        for (int mt = 0; mt < 2; ++mt) {
            const int r = wm * 32 + mt * 16 + g;
            afv[mt][0] = *reinterpret_cast<const float4*>(A + r * 48 + 4 * tg);
            afv[mt][1] = *reinterpret_cast<const float4*>(A + (r + 8) * 48 + 4 * tg);
            afv[mt][2] = *reinterpret_cast<const float4*>(A + r * 48 + 4 * (tg + 4));
            afv[mt][3] = *reinterpret_cast<const float4*>(A + (r + 8) * 48 + 4 * (tg + 4));
        }

#pragma unroll
        for (int ks = 0; ks < 4; ++ks) {
            const int c  = ks * 8 + tg;
            const int n0 = wn * 48 + 6 * g;
            // B rows c and c+4: 6 consecutive floats each (sigma remap), 3x LDS.64
            float2 b0[3], b1[3];
#pragma unroll
            for (int h = 0; h < 3; ++h) {
                b0[h] = *reinterpret_cast<const float2*>(Bv + c * 104 + n0 + 2 * h);
                b1[h] = *reinterpret_cast<const float2*>(Bv + (c + 4) * 104 + n0 + 2 * h);
            }
            uint32_t af[2][4];
#pragma unroll
            for (int mt = 0; mt < 2; ++mt) {
                const float* a0 = reinterpret_cast<const float*>(&afv[mt][0]);
                const float* a1 = reinterpret_cast<const float*>(&afv[mt][1]);
                const float* a2 = reinterpret_cast<const float*>(&afv[mt][2]);
                const float* a3 = reinterpret_cast<const float*>(&afv[mt][3]);
                af[mt][0] = __float_as_uint(a0[ks]);
                af[mt][1] = __float_as_uint(a1[ks]);
                af[mt][2] = __float_as_uint(a2[ks]);
                af[mt][3] = __float_as_uint(a3[ks]);
            }
#pragma unroll
            for (int nt = 0; nt < 6; ++nt) {
                const float* p0 = reinterpret_cast<const float*>(b0);
                const float* p1 = reinterpret_cast<const float*>(b1);
                uint32_t bf[2] = { __float_as_uint(p0[nt]), __float_as_uint(p1[nt]) };
                mma8(acc[0][nt], af[0], bf);
                mma8(acc[1][nt], af[1], bf);
            }
        }

        // p output: normalized e, from the smem tile (1/4 duty cycle)
        if ((kc & 3) == dot) {
            const int k0 = kc * 32;
#pragma unroll
            for (int it = 0; it < 3; ++it) {
                const int kk = bkk[it], qc = bqc[it];
                float4 v = *reinterpret_cast<const float4*>(Bv + kk * 104 + qc);
                float4 w;
                w.x = v.x * sinv[qc];
                w.y = v.y * sinv[qc + 1];
                w.z = v.z * sinv[qc + 2];
                w.w = v.w * sinv[qc + 3];
                const int qg = q0 + qc;
                float* dst = pout + (size_t)(k0 + kk) * Q_ + qg;
                if (qg + 3 < Q_) {
                    *reinterpret_cast<float4*>(dst) = w;
                } else {
                    if (qg     < Q_) dst[0] = w.x;
                    if (qg + 1 < Q_) dst[1] = w.y;
                    if (qg + 2 < Q_) dst[2] = w.z;
                    if (qg + 3 < Q_) dst[3] = w.w;
                }
            }
        }
        __syncthreads();
    }

    // epilogue: mem = U * inv[q], with sigma column remap:
    //   mma col j_col = 2*tg + (j&1)  ->  q = wn*48 + 6*j_col + nt
#pragma unroll
    for (int mt = 0; mt < 2; ++mt)
#pragma unroll
        for (int nt = 0; nt < 6; ++nt)
#pragma unroll
            for (int j = 0; j < 4; ++j) {
                int r  = wm * 32 + mt * 16 + ((j & 2) ? (g + 8) : g);
                int cq = wn * 48 + 6 * (tg * 2 + (j & 1)) + nt;
                int qg = q0 + cq;
                if (qg < Q_)
                    out_mem[((size_t)b * DO + do0 + r) * Q_ + qg] =
                        acc[mt][nt][j] * sinv[cq];
            }
}

extern "C" void kernel_launch(void* const* d_in, const int* in_sizes, int n_in,
                              void* d_out, int out_size) {
    const float* m_in  = (const float*)d_in[0];
    const float* m_out = (const float*)d_in[1];
    const float* q_in  = (const float*)d_in[2];
    const float* cst   = (const float*)d_in[3];
    float* out = (float*)d_out;

    cudaFuncSetAttribute(k3_out, cudaFuncAttributeMaxDynamicSharedMemorySize,
                         SMEMF * 4);

    k0_round<<<(B_ * DO * K_) / (4 * 256), 256>>>(m_out);   // exact division
    k1_scores<<<dim3(NKT, NQT, B_), 256>>>(m_in, q_in);
    k2_inv<<<(B_ * QPAD + 255) / 256, 256>>>(cst);
    k3_out<<<dim3(4, NQT, B_), 256, SMEMF * 4>>>(out, out + MEM_ELEMS);
}

// round 14
// speedup vs baseline: 1.4633x; 1.1142x over previous
#include <cuda_runtime.h>
#include <cstdint>
#include <cstddef>

constexpr int B_  = 4;
constexpr int DE  = 128;
constexpr int DO  = 512;
constexpr int K_  = 12960;   // 8*30*54 = 405*32
constexpr int Q_  = 1620;    // 30*54

constexpr int QT   = 96;
constexpr int NQT  = 17;          // ceil(1620/96)
constexpr int QPAD = NQT * QT;    // 1632
constexpr int KT   = 128;
constexpr int NKT  = 102;         // ceil(12960/128)

constexpr int MEM_ELEMS = B_ * DO * Q_;
constexpr float SCALE = 0.088388347648318447f;  // 1/sqrt(128)

// scratch: static device globals (no runtime allocation)
// g_e padded: K3's cp.async tail chunks may read up to 48B past the last row.
__device__ float g_e[(size_t)B_ * K_ * Q_ + 64];
__device__ float g_mo[(size_t)B_ * DO * K_];          // tf32-pre-rounded m_out
__device__ float g_part[(size_t)B_ * NKT * QPAD];
__device__ float g_inv[(size_t)B_ * QPAD];

__device__ __forceinline__ uint32_t f2tf(float x) {
    uint32_t u;
    asm("cvt.rna.tf32.f32 %0, %1;" : "=r"(u) : "f"(x));
    return u;
}

// D(16x8) += A(16x8 row) * B(8x8 col), tf32 in, fp32 accum
__device__ __forceinline__ void mma8(float* c, const uint32_t* a, const uint32_t* b) {
    asm volatile(
        "mma.sync.aligned.m16n8k8.row.col.f32.tf32.tf32.f32 "
        "{%0,%1,%2,%3}, {%4,%5,%6,%7}, {%8,%9}, {%0,%1,%2,%3};\n"
        : "+f"(c[0]), "+f"(c[1]), "+f"(c[2]), "+f"(c[3])
        : "r"(a[0]), "r"(a[1]), "r"(a[2]), "r"(a[3]),
          "r"(b[0]), "r"(b[1]));
}

__device__ __forceinline__ uint32_t s2u(const void* p) {
    return (uint32_t)__cvta_generic_to_shared(p);
}
__device__ __forceinline__ void cpa16(uint32_t dst, const float* src) {
    asm volatile("cp.async.cg.shared.global [%0], [%1], 16;\n" :: "r"(dst), "l"(src));
}
__device__ __forceinline__ void cpcommit() {
    asm volatile("cp.async.commit_group;\n");
}

// ===========================================================================
// K0: pre-round m_out to tf32 (so K3's cp.async path needs no conversion)
// ===========================================================================
__global__ void k0_round(const float* __restrict__ src)
{
    size_t i = ((size_t)blockIdx.x * 256 + threadIdx.x) * 4;
    float4 v = *reinterpret_cast<const float4*>(src + i);
    v.x = __uint_as_float(f2tf(v.x));
    v.y = __uint_as_float(f2tf(v.y));
    v.z = __uint_as_float(f2tf(v.z));
    v.w = __uint_as_float(f2tf(v.w));
    *reinterpret_cast<float4*>(g_mo + i) = v;
}

// ===========================================================================
// K1: e = exp(S/sqrt(DE)); S = m_in^T q_in. Column partial sums to g_part.
// g_e stored tf32-ROUNDED so K3 consumes raw bits exactly.
// R10 structure; tiles now k-major with LDG.128/STS.128 and u32-offset
// descriptors (kills the div/mod + 64-bit address ALU that bound R8's K1).
//   A smem: [dd 32][kk 128] pad 136  (frag As[c*136+r]: conflict-free)
//   B smem: [dd 32][q 96]   pad 104  (frag Bs[c*104+n]: conflict-free)
// ===========================================================================
__global__ __launch_bounds__(256, 2)
void k1_scores(const float* __restrict__ m_in, const float* __restrict__ q_in)
{
    __shared__ uint32_t As[32 * 136];   // 4352 u32
    __shared__ uint32_t Bs[32 * 104];   // 3328 u32
    __shared__ float    cs[4 * 96];

    const int tid  = threadIdx.x;
    const int wid  = tid >> 5;
    const int lane = tid & 31;
    const int g    = lane >> 2;
    const int tg   = lane & 3;
    const int wm   = wid & 3;
    const int wn   = wid >> 2;

    const int kt = blockIdx.x;
    const int qt = blockIdx.y;
    const int b  = blockIdx.z;
    const int k0 = kt * KT;
    const int q0 = qt * QT;

    const float* mi = m_in + (size_t)b * DE * K_;
    const float* qi = q_in + (size_t)b * DE * Q_;

    // per-thread chunk descriptors (u32 element offsets; all < 1.7M)
    uint32_t aoff[4], asm_[4]; bool aval[4];
#pragma unroll
    for (int it = 0; it < 4; ++it) {
        int i   = tid + it * 256;        // 1024 chunks: [dd 32][kkc 32]
        int dd  = i >> 5;
        int kk  = (i & 31) * 4;
        aval[it] = (k0 + kk) < K_;       // chunk-aligned: K_ % 4 == 0
        aoff[it] = (uint32_t)(dd * K_ + k0 + kk);
        asm_[it] = (uint32_t)(dd * 136 + kk);
    }
    uint32_t boff[3], bsm_[3]; bool bval[3];
#pragma unroll
    for (int it = 0; it < 3; ++it) {
        int i   = tid + it * 256;        // 768 chunks: [dd 32][qc 24]
        int dd  = i / 24;
        int q   = (i - dd * 24) * 4;
        bval[it] = (q0 + q) < Q_;        // chunk-aligned: Q_ % 4 == 0
        boff[it] = (uint32_t)(dd * Q_ + q0 + q);
        bsm_[it] = (uint32_t)(dd * 104 + q);
    }

    float acc[2][6][4];
#pragma unroll
    for (int mt = 0; mt < 2; ++mt)
#pragma unroll
        for (int nt = 0; nt < 6; ++nt)
#pragma unroll
            for (int j = 0; j < 4; ++j) acc[mt][nt][j] = 0.f;

    for (int dc = 0; dc < 4; ++dc) {
#pragma unroll
        for (int it = 0; it < 4; ++it) {
            uint4 w = {0u, 0u, 0u, 0u};
            if (aval[it]) {
                float4 v = *reinterpret_cast<const float4*>(mi + aoff[it]);
                w.x = f2tf(v.x); w.y = f2tf(v.y); w.z = f2tf(v.z); w.w = f2tf(v.w);
            }
            *reinterpret_cast<uint4*>(&As[asm_[it]]) = w;
            aoff[it] += 32u * K_;
        }
#pragma unroll
        for (int it = 0; it < 3; ++it) {
            uint4 w = {0u, 0u, 0u, 0u};
            if (bval[it]) {
                float4 v = *reinterpret_cast<const float4*>(qi + boff[it]);
                w.x = f2tf(v.x); w.y = f2tf(v.y); w.z = f2tf(v.z); w.w = f2tf(v.w);
            }
            *reinterpret_cast<uint4*>(&Bs[bsm_[it]]) = w;
            boff[it] += 32u * Q_;
        }
        __syncthreads();

#pragma unroll
        for (int ks = 0; ks < 4; ++ks) {
            const int c = ks * 8 + tg;
            uint32_t af[2][4];
#pragma unroll
            for (int mt = 0; mt < 2; ++mt) {
                int r = wm * 32 + mt * 16 + g;
                af[mt][0] = As[c * 136 + r];
                af[mt][1] = As[c * 136 + r + 8];
                af[mt][2] = As[(c + 4) * 136 + r];
                af[mt][3] = As[(c + 4) * 136 + r + 8];
            }
#pragma unroll
            for (int nt = 0; nt < 6; ++nt) {
                int n = wn * 48 + nt * 8 + g;
                uint32_t bf[2] = { Bs[c * 104 + n], Bs[(c + 4) * 104 + n] };
                mma8(acc[0][nt], af[0], bf);
                mma8(acc[1][nt], af[1], bf);
            }
        }
        __syncthreads();
    }

    // exp + masked column sums
    float ls[6][2];
#pragma unroll
    for (int nt = 0; nt < 6; ++nt) { ls[nt][0] = 0.f; ls[nt][1] = 0.f; }

#pragma unroll
    for (int mt = 0; mt < 2; ++mt)
#pragma unroll
        for (int nt = 0; nt < 6; ++nt)
#pragma unroll
            for (int j = 0; j < 4; ++j) {
                int r  = wm * 32 + mt * 16 + ((j & 2) ? (g + 8) : g);
                int kg = k0 + r;
                float e = (kg < K_) ? __expf(acc[mt][nt][j] * SCALE) : 0.f;
                acc[mt][nt][j] = e;
                ls[nt][j & 1] += e;
            }

#pragma unroll
    for (int nt = 0; nt < 6; ++nt)
#pragma unroll
        for (int p = 0; p < 2; ++p) {
            float v = ls[nt][p];
            v += __shfl_xor_sync(0xffffffffu, v, 4);
            v += __shfl_xor_sync(0xffffffffu, v, 8);
            v += __shfl_xor_sync(0xffffffffu, v, 16);
            if (g == 0) cs[wm * 96 + wn * 48 + nt * 8 + tg * 2 + p] = v;
        }
    __syncthreads();

    if (tid < 96) {
        float s = cs[tid] + cs[96 + tid] + cs[192 + tid] + cs[288 + tid];
        g_part[((size_t)b * NKT + kt) * QPAD + qt * QT + tid] = s;
    }

    // stage e through smem for coalesced g_e stores (tf32-rounded)
    float* stg = reinterpret_cast<float*>(As);   // 32 x (stride 100) = 3200 <= 4352
#pragma unroll 1
    for (int chunk = 0; chunk < 4; ++chunk) {
        __syncthreads();
        if (wm == chunk) {
#pragma unroll
            for (int mt = 0; mt < 2; ++mt)
#pragma unroll
                for (int nt = 0; nt < 6; ++nt)
#pragma unroll
                    for (int j = 0; j < 4; ++j) {
                        int r = mt * 16 + ((j & 2) ? (g + 8) : g);
                        int c = wn * 48 + nt * 8 + tg * 2 + (j & 1);
                        stg[r * 100 + c] = __uint_as_float(f2tf(acc[mt][nt][j]));
                    }
        }
        __syncthreads();
        for (int i = tid; i < 32 * 96; i += 256) {
            int r = i / 96, c = i - r * 96;
            int kg = k0 + chunk * 32 + r;
            int qg = q0 + c;
            if (kg < K_ && qg < Q_)
                g_e[((size_t)b * K_ + kg) * Q_ + qg] = stg[r * 100 + c];
        }
    }
}

// ===========================================================================
// K2: g_inv[b,q] = 1 / (exp(const) + sum_kt g_part)
// ===========================================================================
__global__ void k2_inv(const float* __restrict__ cst)
{
    int t = blockIdx.x * blockDim.x + threadIdx.x;
    if (t >= B_ * QPAD) return;
    int b  = t / QPAD;
    int qp = t - b * QPAD;
    float d = expf(cst[0]);
    const float* gp = g_part + (size_t)b * NKT * QPAD + qp;
#pragma unroll 4
    for (int kt = 0; kt < NKT; ++kt) d += gp[(size_t)kt * QPAD];
    g_inv[t] = 1.f / d;
}

// ===========================================================================
// K3 (R10 verbatim — best of four measured variants):
// U = g_mo @ g_e via 2-stage cp.async pipeline (no cvt in loop),
// mem = U*inv[q] in epilogue; p = g_e*inv from smem B tile (1/4 duty cycle).
// Block tile M=128(d_o) x N=96(q); 405 k-chunks of 32 (exact).
// ===========================================================================
constexpr int ASTR  = 128 * 36;   // floats per A buffer (stride 36: conflict-free)
constexpr int BSTR  = 32 * 104;   // floats per B buffer (stride 104: conflict-free)
constexpr int SMEMF = 2 * ASTR + 2 * BSTR + 96;   // 15968 floats = 63872 B

__global__ __launch_bounds__(256, 2)
void k3_out(float* __restrict__ out_mem, float* __restrict__ out_p)
{
    extern __shared__ float sm[];
    float* Ab   = sm;
    float* Bb   = sm + 2 * ASTR;
    float* sinv = sm + 2 * ASTR + 2 * BSTR;

    const int tid  = threadIdx.x;
    const int wid  = tid >> 5;
    const int lane = tid & 31;
    const int g    = lane >> 2;
    const int tg   = lane & 3;
    const int wm   = wid & 3;
    const int wn   = wid >> 2;

    const int dot = blockIdx.x;   // 0..3
    const int qt  = blockIdx.y;   // 0..16
    const int b   = blockIdx.z;
    const int q0  = qt * QT;
    const int do0 = dot * 128;

    if (tid < 96) sinv[tid] = g_inv[(size_t)b * QPAD + q0 + tid];

    const float* asrc[4]; uint32_t aoff[4];
#pragma unroll
    for (int it = 0; it < 4; ++it) {
        int i = tid + it * 256;          // A: 128 rows x 32 floats = 1024 x 16B
        int row = i >> 3;
        int kc4 = (i & 7) * 4;
        asrc[it] = g_mo + ((size_t)b * DO + do0 + row) * K_ + kc4;
        aoff[it] = (uint32_t)((row * 36 + kc4) * 4);
    }
    const float* bsrc[3]; uint32_t boff[3]; int bkk[3], bqc[3];
#pragma unroll
    for (int it = 0; it < 3; ++it) {
        int i  = tid + it * 256;         // B: 32 rows x 96 floats = 768 x 16B
        int kk = i / 24;
        int qc = (i - kk * 24) * 4;
        bkk[it] = kk; bqc[it] = qc;
        bsrc[it] = g_e + (size_t)b * K_ * Q_ + (size_t)kk * Q_ + q0 + qc;
        boff[it] = (uint32_t)((kk * 104 + qc) * 4);
    }
    const uint32_t Abase = s2u(Ab);
    const uint32_t Bbase = s2u(Bb);

    float acc[2][6][4];
#pragma unroll
    for (int mt = 0; mt < 2; ++mt)
#pragma unroll
        for (int nt = 0; nt < 6; ++nt)
#pragma unroll
            for (int j = 0; j < 4; ++j) acc[mt][nt][j] = 0.f;

    // prologue: stage kc=0 into buffer 0
#pragma unroll
    for (int it = 0; it < 4; ++it) cpa16(Abase + aoff[it], asrc[it]);
#pragma unroll
    for (int it = 0; it < 3; ++it) cpa16(Bbase + boff[it], bsrc[it]);
    cpcommit();
#pragma unroll
    for (int it = 0; it < 4; ++it) asrc[it] += 32;
#pragma unroll
    for (int it = 0; it < 3; ++it) bsrc[it] += (size_t)32 * Q_;

    float* pout = out_p + (size_t)b * K_ * Q_;

#pragma unroll 1
    for (int kc = 0; kc < 405; ++kc) {
        if (kc < 404) {
            const uint32_t sa = Abase + ((kc + 1) & 1) * (ASTR * 4);
            const uint32_t sb = Bbase + ((kc + 1) & 1) * (BSTR * 4);
#pragma unroll
            for (int it = 0; it < 4; ++it) { cpa16(sa + aoff[it], asrc[it]); asrc[it] += 32; }
#pragma unroll
            for (int it = 0; it < 3; ++it) { cpa16(sb + boff[it], bsrc[it]); bsrc[it] += (size_t)32 * Q_; }
            cpcommit();
            asm volatile("cp.async.wait_group 1;\n" ::: "memory");
        } else {
            asm volatile("cp.async.wait_group 0;\n" ::: "memory");
        }
        __syncthreads();

        const float* A  = Ab + (kc & 1) * ASTR;
        const float* Bv = Bb + (kc & 1) * BSTR;

#pragma unroll
        for (int ks = 0; ks < 4; ++ks) {
            const int c = ks * 8 + tg;
            uint32_t af[2][4];
#pragma unroll
            for (int mt = 0; mt < 2; ++mt) {
                int r = wm * 32 + mt * 16 + g;
                af[mt][0] = __float_as_uint(A[r * 36 + c]);
                af[mt][1] = __float_as_uint(A[(r + 8) * 36 + c]);
                af[mt][2] = __float_as_uint(A[r * 36 + c + 4]);
                af[mt][3] = __float_as_uint(A[(r + 8) * 36 + c + 4]);
            }
#pragma unroll
            for (int nt = 0; nt < 6; ++nt) {
                int n = wn * 48 + nt * 8 + g;
                uint32_t bf[2] = { __float_as_uint(Bv[c * 104 + n]),
                                   __float_as_uint(Bv[(c + 4) * 104 + n]) };
                mma8(acc[0][nt], af[0], bf);
                mma8(acc[1][nt], af[1], bf);
            }
        }

        // p output: normalized e, from the smem tile (1/4 duty cycle)
        if ((kc & 3) == dot) {
            const int k0 = kc * 32;
#pragma unroll
            for (int it = 0; it < 3; ++it) {
                const int kk = bkk[it], qc = bqc[it];
                float4 v = *reinterpret_cast<const float4*>(Bv + kk * 104 + qc);
                float4 w;
                w.x = v.x * sinv[qc];
                w.y = v.y * sinv[qc + 1];
                w.z = v.z * sinv[qc + 2];
                w.w = v.w * sinv[qc + 3];
                const int qg = q0 + qc;
                float* dst = pout + (size_t)(k0 + kk) * Q_ + qg;
                if (qg + 3 < Q_) {
                    *reinterpret_cast<float4*>(dst) = w;
                } else {
                    if (qg     < Q_) dst[0] = w.x;
                    if (qg + 1 < Q_) dst[1] = w.y;
                    if (qg + 2 < Q_) dst[2] = w.z;
                    if (qg + 3 < Q_) dst[3] = w.w;
                }
            }
        }
        __syncthreads();
    }

    // epilogue: mem = U * inv[q]
#pragma unroll
    for (int mt = 0; mt < 2; ++mt)
#pragma unroll
        for (int nt = 0; nt < 6; ++nt)
#pragma unroll
            for (int j = 0; j < 4; ++j) {
                int r  = wm * 32 + mt * 16 + ((j & 2) ? (g + 8) : g);
                int cq = wn * 48 + nt * 8 + tg * 2 + (j & 1);
                int qg = q0 + cq;
                if (qg < Q_)
                    out_mem[((size_t)b * DO + do0 + r) * Q_ + qg] =
                        acc[mt][nt][j] * sinv[cq];
            }
}

extern "C" void kernel_launch(void* const* d_in, const int* in_sizes, int n_in,
                              void* d_out, int out_size) {
    const float* m_in  = (const float*)d_in[0];
    const float* m_out = (const float*)d_in[1];
    const float* q_in  = (const float*)d_in[2];
    const float* cst   = (const float*)d_in[3];
    float* out = (float*)d_out;

    cudaFuncSetAttribute(k3_out, cudaFuncAttributeMaxDynamicSharedMemorySize,
                         SMEMF * 4);

    k0_round<<<(B_ * DO * K_) / (4 * 256), 256>>>(m_out);   // exact division
    k1_scores<<<dim3(NKT, NQT, B_), 256>>>(m_in, q_in);
    k2_inv<<<(B_ * QPAD + 255) / 256, 256>>>(cst);
    k3_out<<<dim3(4, NQT, B_), 256, SMEMF * 4>>>(out, out + MEM_ELEMS);
}

// round 15
// speedup vs baseline: 1.5034x; 1.0274x over previous
#include <cuda_runtime.h>
#include <cstdint>
#include <cstddef>

constexpr int B_  = 4;
constexpr int DE  = 128;
constexpr int DO  = 512;
constexpr int K_  = 12960;   // 8*30*54 = 405*32
constexpr int Q_  = 1620;    // 30*54

constexpr int QT   = 96;
constexpr int NQT  = 17;          // ceil(1620/96)
constexpr int QPAD = NQT * QT;    // 1632
constexpr int KT   = 128;
constexpr int NKT  = 102;         // ceil(12960/128)

constexpr int MEM_ELEMS = B_ * DO * Q_;
constexpr float SCALE = 0.088388347648318447f;  // 1/sqrt(128)

// scratch: static device globals (no runtime allocation)
// g_e padded: K3's cp.async tail chunks may read up to 48B past the last row.
__device__ float g_e[(size_t)B_ * K_ * Q_ + 64];
__device__ float g_mo[(size_t)B_ * DO * K_];          // tf32-pre-rounded m_out
__device__ float g_part[(size_t)B_ * NKT * QPAD];
__device__ float g_inv[(size_t)B_ * QPAD];

__device__ __forceinline__ uint32_t f2tf(float x) {
    uint32_t u;
    asm("cvt.rna.tf32.f32 %0, %1;" : "=r"(u) : "f"(x));
    return u;
}

// D(16x8) += A(16x8 row) * B(8x8 col), tf32 in, fp32 accum
__device__ __forceinline__ void mma8(float* c, const uint32_t* a, const uint32_t* b) {
    asm volatile(
        "mma.sync.aligned.m16n8k8.row.col.f32.tf32.tf32.f32 "
        "{%0,%1,%2,%3}, {%4,%5,%6,%7}, {%8,%9}, {%0,%1,%2,%3};\n"
        : "+f"(c[0]), "+f"(c[1]), "+f"(c[2]), "+f"(c[3])
        : "r"(a[0]), "r"(a[1]), "r"(a[2]), "r"(a[3]),
          "r"(b[0]), "r"(b[1]));
}

__device__ __forceinline__ uint32_t s2u(const void* p) {
    return (uint32_t)__cvta_generic_to_shared(p);
}
__device__ __forceinline__ void cpa16(uint32_t dst, const float* src) {
    asm volatile("cp.async.cg.shared.global [%0], [%1], 16;\n" :: "r"(dst), "l"(src));
}
__device__ __forceinline__ void cpcommit() {
    asm volatile("cp.async.commit_group;\n");
}

// ===========================================================================
// K0: pre-round m_out to tf32 (so K3's cp.async path needs no conversion)
// ===========================================================================
__global__ void k0_round(const float* __restrict__ src)
{
    size_t i = ((size_t)blockIdx.x * 256 + threadIdx.x) * 4;
    float4 v = *reinterpret_cast<const float4*>(src + i);
    v.x = __uint_as_float(f2tf(v.x));
    v.y = __uint_as_float(f2tf(v.y));
    v.z = __uint_as_float(f2tf(v.z));
    v.w = __uint_as_float(f2tf(v.w));
    *reinterpret_cast<float4*>(g_mo + i) = v;
}

// ===========================================================================
// K1: e = exp(S/sqrt(DE)); S = m_in^T q_in. Column partial sums to g_part.
// g_e stored tf32-ROUNDED so K3 consumes raw bits exactly.
// NEW: cp.async double-buffered mainloop (K3's proven R10 pattern).
// Tiles land as RAW fp32; cvt.rna moves to the fragment-load path
// (bit-identical results — same rounding points, same order).
//   A smem: [dd 32][kk 128] pad 136  (frag Af[c*136+r]: conflict-free)
//   B smem: [dd 32][q 96]   pad 104  (frag Bf[c*104+n]: conflict-free)
// OOB chunks zeroed ONCE per buffer (cp.async never writes them).
// ===========================================================================
constexpr int K1A = 32 * 136;   // floats per A buffer
constexpr int K1B = 32 * 104;   // floats per B buffer
constexpr int K1SMEMF = 2 * K1A + 2 * K1B + 384;   // 15744 floats = 62976 B

__global__ __launch_bounds__(256, 2)
void k1_scores(const float* __restrict__ m_in, const float* __restrict__ q_in)
{
    extern __shared__ float smf[];
    float* Af = smf;                    // 2 buffers
    float* Bf = smf + 2 * K1A;          // 2 buffers
    float* cs = smf + 2 * K1A + 2 * K1B;

    const int tid  = threadIdx.x;
    const int wid  = tid >> 5;
    const int lane = tid & 31;
    const int g    = lane >> 2;
    const int tg   = lane & 3;
    const int wm   = wid & 3;
    const int wn   = wid >> 2;

    const int kt = blockIdx.x;
    const int qt = blockIdx.y;
    const int b  = blockIdx.z;
    const int k0 = kt * KT;
    const int q0 = qt * QT;

    const float* mi = m_in + (size_t)b * DE * K_;
    const float* qi = q_in + (size_t)b * DE * Q_;

    // per-thread chunk descriptors (u32 element offsets)
    uint32_t aoff[4], asmo[4]; bool aval[4];
#pragma unroll
    for (int it = 0; it < 4; ++it) {
        int i   = tid + it * 256;        // 1024 chunks: [dd 32][kkc 32]
        int dd  = i >> 5;
        int kk  = (i & 31) * 4;
        aval[it] = (k0 + kk) < K_;       // K_ % 4 == 0: chunk fully valid or not
        aoff[it] = (uint32_t)(dd * K_ + k0 + kk);
        asmo[it] = (uint32_t)(dd * 136 + kk);
    }
    uint32_t boff[3], bsmo[3]; bool bval[3];
#pragma unroll
    for (int it = 0; it < 3; ++it) {
        int i   = tid + it * 256;        // 768 chunks: [dd 32][qc 24]
        int dd  = i / 24;
        int q   = (i - dd * 24) * 4;
        bval[it] = (q0 + q) < Q_;        // Q_ % 4 == 0
        boff[it] = (uint32_t)(dd * Q_ + q0 + q);
        bsmo[it] = (uint32_t)(dd * 104 + q);
    }

    // zero OOB chunks once in BOTH buffers (they persist across all dc)
    const float4 z4 = {0.f, 0.f, 0.f, 0.f};
#pragma unroll
    for (int it = 0; it < 4; ++it)
        if (!aval[it]) {
            *reinterpret_cast<float4*>(Af + asmo[it])        = z4;
            *reinterpret_cast<float4*>(Af + K1A + asmo[it])  = z4;
        }
#pragma unroll
    for (int it = 0; it < 3; ++it)
        if (!bval[it]) {
            *reinterpret_cast<float4*>(Bf + bsmo[it])        = z4;
            *reinterpret_cast<float4*>(Bf + K1B + bsmo[it])  = z4;
        }

    const uint32_t Abase = s2u(Af);
    const uint32_t Bbase = s2u(Bf);

    float acc[2][6][4];
#pragma unroll
    for (int mt = 0; mt < 2; ++mt)
#pragma unroll
        for (int nt = 0; nt < 6; ++nt)
#pragma unroll
            for (int j = 0; j < 4; ++j) acc[mt][nt][j] = 0.f;

    // prologue: stage dc=0 into buffer 0
#pragma unroll
    for (int it = 0; it < 4; ++it) {
        if (aval[it]) cpa16(Abase + asmo[it] * 4, mi + aoff[it]);
        aoff[it] += 32u * K_;
    }
#pragma unroll
    for (int it = 0; it < 3; ++it) {
        if (bval[it]) cpa16(Bbase + bsmo[it] * 4, qi + boff[it]);
        boff[it] += 32u * Q_;
    }
    cpcommit();

#pragma unroll
    for (int dc = 0; dc < 4; ++dc) {
        if (dc < 3) {     // early-issue dc+1 into the other buffer
            const uint32_t sa = Abase + ((dc + 1) & 1) * (K1A * 4);
            const uint32_t sb = Bbase + ((dc + 1) & 1) * (K1B * 4);
#pragma unroll
            for (int it = 0; it < 4; ++it) {
                if (aval[it]) cpa16(sa + asmo[it] * 4, mi + aoff[it]);
                aoff[it] += 32u * K_;
            }
#pragma unroll
            for (int it = 0; it < 3; ++it) {
                if (bval[it]) cpa16(sb + bsmo[it] * 4, qi + boff[it]);
                boff[it] += 32u * Q_;
            }
            cpcommit();
            asm volatile("cp.async.wait_group 1;\n" ::: "memory");
        } else {
            asm volatile("cp.async.wait_group 0;\n" ::: "memory");
        }
        __syncthreads();

        const float* A  = Af + (dc & 1) * K1A;
        const float* Bv = Bf + (dc & 1) * K1B;

#pragma unroll
        for (int ks = 0; ks < 4; ++ks) {
            const int c = ks * 8 + tg;
            uint32_t af[2][4];
#pragma unroll
            for (int mt = 0; mt < 2; ++mt) {
                int r = wm * 32 + mt * 16 + g;
                af[mt][0] = f2tf(A[c * 136 + r]);
                af[mt][1] = f2tf(A[c * 136 + r + 8]);
                af[mt][2] = f2tf(A[(c + 4) * 136 + r]);
                af[mt][3] = f2tf(A[(c + 4) * 136 + r + 8]);
            }
#pragma unroll
            for (int nt = 0; nt < 6; ++nt) {
                int n = wn * 48 + nt * 8 + g;
                uint32_t bf[2] = { f2tf(Bv[c * 104 + n]), f2tf(Bv[(c + 4) * 104 + n]) };
                mma8(acc[0][nt], af[0], bf);
                mma8(acc[1][nt], af[1], bf);
            }
        }
        __syncthreads();
    }

    // exp + masked column sums
    float ls[6][2];
#pragma unroll
    for (int nt = 0; nt < 6; ++nt) { ls[nt][0] = 0.f; ls[nt][1] = 0.f; }

#pragma unroll
    for (int mt = 0; mt < 2; ++mt)
#pragma unroll
        for (int nt = 0; nt < 6; ++nt)
#pragma unroll
            for (int j = 0; j < 4; ++j) {
                int r  = wm * 32 + mt * 16 + ((j & 2) ? (g + 8) : g);
                int kg = k0 + r;
                float e = (kg < K_) ? __expf(acc[mt][nt][j] * SCALE) : 0.f;
                acc[mt][nt][j] = e;
                ls[nt][j & 1] += e;
            }

#pragma unroll
    for (int nt = 0; nt < 6; ++nt)
#pragma unroll
        for (int p = 0; p < 2; ++p) {
            float v = ls[nt][p];
            v += __shfl_xor_sync(0xffffffffu, v, 4);
            v += __shfl_xor_sync(0xffffffffu, v, 8);
            v += __shfl_xor_sync(0xffffffffu, v, 16);
            if (g == 0) cs[wm * 96 + wn * 48 + nt * 8 + tg * 2 + p] = v;
        }
    __syncthreads();

    if (tid < 96) {
        float s = cs[tid] + cs[96 + tid] + cs[192 + tid] + cs[288 + tid];
        g_part[((size_t)b * NKT + kt) * QPAD + qt * QT + tid] = s;
    }

    // stage e through smem for coalesced g_e stores (tf32-rounded)
    float* stg = Af;   // 32 x (stride 100) = 3200 <= K1A
#pragma unroll 1
    for (int chunk = 0; chunk < 4; ++chunk) {
        __syncthreads();
        if (wm == chunk) {
#pragma unroll
            for (int mt = 0; mt < 2; ++mt)
#pragma unroll
                for (int nt = 0; nt < 6; ++nt)
#pragma unroll
                    for (int j = 0; j < 4; ++j) {
                        int r = mt * 16 + ((j & 2) ? (g + 8) : g);
                        int c = wn * 48 + nt * 8 + tg * 2 + (j & 1);
                        stg[r * 100 + c] = __uint_as_float(f2tf(acc[mt][nt][j]));
                    }
        }
        __syncthreads();
        for (int i = tid; i < 32 * 96; i += 256) {
            int r = i / 96, c = i - r * 96;
            int kg = k0 + chunk * 32 + r;
            int qg = q0 + c;
            if (kg < K_ && qg < Q_)
                g_e[((size_t)b * K_ + kg) * Q_ + qg] = stg[r * 100 + c];
        }
    }
}

// ===========================================================================
// K2: g_inv[b,q] = 1 / (exp(const) + sum_kt g_part)
// ===========================================================================
__global__ void k2_inv(const float* __restrict__ cst)
{
    int t = blockIdx.x * blockDim.x + threadIdx.x;
    if (t >= B_ * QPAD) return;
    int b  = t / QPAD;
    int qp = t - b * QPAD;
    float d = expf(cst[0]);
    const float* gp = g_part + (size_t)b * NKT * QPAD + qp;
#pragma unroll 4
    for (int kt = 0; kt < NKT; ++kt) d += gp[(size_t)kt * QPAD];
    g_inv[t] = 1.f / d;
}

// ===========================================================================
// K3 (R10 verbatim — measured plateau 719us, best of four variants):
// U = g_mo @ g_e via 2-stage cp.async pipeline (no cvt in loop),
// mem = U*inv[q] in epilogue; p = g_e*inv from smem B tile (1/4 duty cycle).
// Block tile M=128(d_o) x N=96(q); 405 k-chunks of 32 (exact).
// ===========================================================================
constexpr int ASTR  = 128 * 36;   // floats per A buffer (stride 36: conflict-free)
constexpr int BSTR  = 32 * 104;   // floats per B buffer (stride 104: conflict-free)
constexpr int SMEMF = 2 * ASTR + 2 * BSTR + 96;   // 15968 floats = 63872 B

__global__ __launch_bounds__(256, 2)
void k3_out(float* __restrict__ out_mem, float* __restrict__ out_p)
{
    extern __shared__ float sm[];
    float* Ab   = sm;
    float* Bb   = sm + 2 * ASTR;
    float* sinv = sm + 2 * ASTR + 2 * BSTR;

    const int tid  = threadIdx.x;
    const int wid  = tid >> 5;
    const int lane = tid & 31;
    const int g    = lane >> 2;
    const int tg   = lane & 3;
    const int wm   = wid & 3;
    const int wn   = wid >> 2;

    const int dot = blockIdx.x;   // 0..3
    const int qt  = blockIdx.y;   // 0..16
    const int b   = blockIdx.z;
    const int q0  = qt * QT;
    const int do0 = dot * 128;

    if (tid < 96) sinv[tid] = g_inv[(size_t)b * QPAD + q0 + tid];

    const float* asrc[4]; uint32_t aoff[4];
#pragma unroll
    for (int it = 0; it < 4; ++it) {
        int i = tid + it * 256;          // A: 128 rows x 32 floats = 1024 x 16B
        int row = i >> 3;
        int kc4 = (i & 7) * 4;
        asrc[it] = g_mo + ((size_t)b * DO + do0 + row) * K_ + kc4;
        aoff[it] = (uint32_t)((row * 36 + kc4) * 4);
    }
    const float* bsrc[3]; uint32_t boff[3]; int bkk[3], bqc[3];
#pragma unroll
    for (int it = 0; it < 3; ++it) {
        int i  = tid + it * 256;         // B: 32 rows x 96 floats = 768 x 16B
        int kk = i / 24;
        int qc = (i - kk * 24) * 4;
        bkk[it] = kk; bqc[it] = qc;
        bsrc[it] = g_e + (size_t)b * K_ * Q_ + (size_t)kk * Q_ + q0 + qc;
        boff[it] = (uint32_t)((kk * 104 + qc) * 4);
    }
    const uint32_t Abase = s2u(Ab);
    const uint32_t Bbase = s2u(Bb);

    float acc[2][6][4];
#pragma unroll
    for (int mt = 0; mt < 2; ++mt)
#pragma unroll
        for (int nt = 0; nt < 6; ++nt)
#pragma unroll
            for (int j = 0; j < 4; ++j) acc[mt][nt][j] = 0.f;

    // prologue: stage kc=0 into buffer 0
#pragma unroll
    for (int it = 0; it < 4; ++it) cpa16(Abase + aoff[it], asrc[it]);
#pragma unroll
    for (int it = 0; it < 3; ++it) cpa16(Bbase + boff[it], bsrc[it]);
    cpcommit();
#pragma unroll
    for (int it = 0; it < 4; ++it) asrc[it] += 32;
#pragma unroll
    for (int it = 0; it < 3; ++it) bsrc[it] += (size_t)32 * Q_;

    float* pout = out_p + (size_t)b * K_ * Q_;

#pragma unroll 1
    for (int kc = 0; kc < 405; ++kc) {
        if (kc < 404) {
            const uint32_t sa = Abase + ((kc + 1) & 1) * (ASTR * 4);
            const uint32_t sb = Bbase + ((kc + 1) & 1) * (BSTR * 4);
#pragma unroll
            for (int it = 0; it < 4; ++it) { cpa16(sa + aoff[it], asrc[it]); asrc[it] += 32; }
#pragma unroll
            for (int it = 0; it < 3; ++it) { cpa16(sb + boff[it], bsrc[it]); bsrc[it] += (size_t)32 * Q_; }
            cpcommit();
            asm volatile("cp.async.wait_group 1;\n" ::: "memory");
        } else {
            asm volatile("cp.async.wait_group 0;\n" ::: "memory");
        }
        __syncthreads();

        const float* A  = Ab + (kc & 1) * ASTR;
        const float* Bv = Bb + (kc & 1) * BSTR;

#pragma unroll
        for (int ks = 0; ks < 4; ++ks) {
            const int c = ks * 8 + tg;
            uint32_t af[2][4];
#pragma unroll
            for (int mt = 0; mt < 2; ++mt) {
                int r = wm * 32 + mt * 16 + g;
                af[mt][0] = __float_as_uint(A[r * 36 + c]);
                af[mt][1] = __float_as_uint(A[(r + 8) * 36 + c]);
                af[mt][2] = __float_as_uint(A[r * 36 + c + 4]);
                af[mt][3] = __float_as_uint(A[(r + 8) * 36 + c + 4]);
            }
#pragma unroll
            for (int nt = 0; nt < 6; ++nt) {
                int n = wn * 48 + nt * 8 + g;
                uint32_t bf[2] = { __float_as_uint(Bv[c * 104 + n]),
                                   __float_as_uint(Bv[(c + 4) * 104 + n]) };
                mma8(acc[0][nt], af[0], bf);
                mma8(acc[1][nt], af[1], bf);
            }
        }

        // p output: normalized e, from the smem tile (1/4 duty cycle)
        if ((kc & 3) == dot) {
            const int k0 = kc * 32;
#pragma unroll
            for (int it = 0; it < 3; ++it) {
                const int kk = bkk[it], qc = bqc[it];
                float4 v = *reinterpret_cast<const float4*>(Bv + kk * 104 + qc);
                float4 w;
                w.x = v.x * sinv[qc];
                w.y = v.y * sinv[qc + 1];
                w.z = v.z * sinv[qc + 2];
                w.w = v.w * sinv[qc + 3];
                const int qg = q0 + qc;
                float* dst = pout + (size_t)(k0 + kk) * Q_ + qg;
                if (qg + 3 < Q_) {
                    *reinterpret_cast<float4*>(dst) = w;
                } else {
                    if (qg     < Q_) dst[0] = w.x;
                    if (qg + 1 < Q_) dst[1] = w.y;
                    if (qg + 2 < Q_) dst[2] = w.z;
                    if (qg + 3 < Q_) dst[3] = w.w;
                }
            }
        }
        __syncthreads();
    }

    // epilogue: mem = U * inv[q]
#pragma unroll
    for (int mt = 0; mt < 2; ++mt)
#pragma unroll
        for (int nt = 0; nt < 6; ++nt)
#pragma unroll
            for (int j = 0; j < 4; ++j) {
                int r  = wm * 32 + mt * 16 + ((j & 2) ? (g + 8) : g);
                int cq = wn * 48 + nt * 8 + tg * 2 + (j & 1);
                int qg = q0 + cq;
                if (qg < Q_)
                    out_mem[((size_t)b * DO + do0 + r) * Q_ + qg] =
                        acc[mt][nt][j] * sinv[cq];
            }
}

extern "C" void kernel_launch(void* const* d_in, const int* in_sizes, int n_in,
                              void* d_out, int out_size) {
    const float* m_in  = (const float*)d_in[0];
    const float* m_out = (const float*)d_in[1];
    const float* q_in  = (const float*)d_in[2];
    const float* cst   = (const float*)d_in[3];
    float* out = (float*)d_out;

    cudaFuncSetAttribute(k1_scores, cudaFuncAttributeMaxDynamicSharedMemorySize,
                         K1SMEMF * 4);
    cudaFuncSetAttribute(k3_out, cudaFuncAttributeMaxDynamicSharedMemorySize,
                         SMEMF * 4);

    k0_round<<<(B_ * DO * K_) / (4 * 256), 256>>>(m_out);   // exact division
    k1_scores<<<dim3(NKT, NQT, B_), 256, K1SMEMF * 4>>>(m_in, q_in);
    k2_inv<<<(B_ * QPAD + 255) / 256, 256>>>(cst);
    k3_out<<<dim3(4, NQT, B_), 256, SMEMF * 4>>>(out, out + MEM_ELEMS);
}

// round 16
// speedup vs baseline: 1.5987x; 1.0634x over previous
#include <cuda_runtime.h>
#include <cstdint>
#include <cstddef>

constexpr int B_  = 4;
constexpr int DE  = 128;
constexpr int DO  = 512;
constexpr int K_  = 12960;   // 8*30*54 = 405*32
constexpr int Q_  = 1620;    // 30*54

constexpr int QT   = 96;
constexpr int NQT  = 17;          // ceil(1620/96)
constexpr int QPAD = NQT * QT;    // 1632
constexpr int KT   = 128;
constexpr int NKT  = 102;         // ceil(12960/128)

constexpr int MEM_ELEMS = B_ * DO * Q_;
constexpr float SCALE = 0.088388347648318447f;  // 1/sqrt(128)

// scratch: static device globals (no runtime allocation)
// g_e padded: K3's cp.async tail chunks may read up to 48B past the last row.
__device__ float g_e[(size_t)B_ * K_ * Q_ + 64];
__device__ float g_part[(size_t)B_ * NKT * QPAD];
__device__ float g_inv[(size_t)B_ * QPAD];

__device__ __forceinline__ uint32_t f2tf(float x) {
    uint32_t u;
    asm("cvt.rna.tf32.f32 %0, %1;" : "=r"(u) : "f"(x));
    return u;
}

// D(16x8) += A(16x8 row) * B(8x8 col), tf32 in, fp32 accum
__device__ __forceinline__ void mma8(float* c, const uint32_t* a, const uint32_t* b) {
    asm volatile(
        "mma.sync.aligned.m16n8k8.row.col.f32.tf32.tf32.f32 "
        "{%0,%1,%2,%3}, {%4,%5,%6,%7}, {%8,%9}, {%0,%1,%2,%3};\n"
        : "+f"(c[0]), "+f"(c[1]), "+f"(c[2]), "+f"(c[3])
        : "r"(a[0]), "r"(a[1]), "r"(a[2]), "r"(a[3]),
          "r"(b[0]), "r"(b[1]));
}

__device__ __forceinline__ uint32_t s2u(const void* p) {
    return (uint32_t)__cvta_generic_to_shared(p);
}
__device__ __forceinline__ void cpa16(uint32_t dst, const float* src) {
    asm volatile("cp.async.cg.shared.global [%0], [%1], 16;\n" :: "r"(dst), "l"(src));
}
__device__ __forceinline__ void cpcommit() {
    asm volatile("cp.async.commit_group;\n");
}

// ===========================================================================
// K1: e = exp(S/sqrt(DE)); S = m_in^T q_in. Column partial sums to g_part.
// g_e stored tf32-ROUNDED so K3 consumes raw bits exactly.
// cp.async double-buffered mainloop (R15-proven). Tiles land RAW fp32;
// cvt.rna on the fragment-load path (bit-identical).
//   A smem: [dd 32][kk 128] pad 136  (frag Af[c*136+r]: conflict-free)
//   B smem: [dd 32][q 96]   pad 104  (frag Bf[c*104+n]: conflict-free)
// OOB chunks zeroed ONCE per buffer (cp.async never writes them).
// NEW: g_e staging stores vectorized to float4 (tails are 4-aligned).
// ===========================================================================
constexpr int K1A = 32 * 136;   // floats per A buffer
constexpr int K1B = 32 * 104;   // floats per B buffer
constexpr int K1SMEMF = 2 * K1A + 2 * K1B + 384;   // 15744 floats = 62976 B

__global__ __launch_bounds__(256, 2)
void k1_scores(const float* __restrict__ m_in, const float* __restrict__ q_in)
{
    extern __shared__ float smf[];
    float* Af = smf;                    // 2 buffers
    float* Bf = smf + 2 * K1A;          // 2 buffers
    float* cs = smf + 2 * K1A + 2 * K1B;

    const int tid  = threadIdx.x;
    const int wid  = tid >> 5;
    const int lane = tid & 31;
    const int g    = lane >> 2;
    const int tg   = lane & 3;
    const int wm   = wid & 3;
    const int wn   = wid >> 2;

    const int kt = blockIdx.x;
    const int qt = blockIdx.y;
    const int b  = blockIdx.z;
    const int k0 = kt * KT;
    const int q0 = qt * QT;

    const float* mi = m_in + (size_t)b * DE * K_;
    const float* qi = q_in + (size_t)b * DE * Q_;

    // per-thread chunk descriptors (u32 element offsets)
    uint32_t aoff[4], asmo[4]; bool aval[4];
#pragma unroll
    for (int it = 0; it < 4; ++it) {
        int i   = tid + it * 256;        // 1024 chunks: [dd 32][kkc 32]
        int dd  = i >> 5;
        int kk  = (i & 31) * 4;
        aval[it] = (k0 + kk) < K_;       // K_ % 4 == 0: chunk fully valid or not
        aoff[it] = (uint32_t)(dd * K_ + k0 + kk);
        asmo[it] = (uint32_t)(dd * 136 + kk);
    }
    uint32_t boff[3], bsmo[3]; bool bval[3];
#pragma unroll
    for (int it = 0; it < 3; ++it) {
        int i   = tid + it * 256;        // 768 chunks: [dd 32][qc 24]
        int dd  = i / 24;
        int q   = (i - dd * 24) * 4;
        bval[it] = (q0 + q) < Q_;        // Q_ % 4 == 0
        boff[it] = (uint32_t)(dd * Q_ + q0 + q);
        bsmo[it] = (uint32_t)(dd * 104 + q);
    }

    // zero OOB chunks once in BOTH buffers (they persist across all dc)
    const float4 z4 = {0.f, 0.f, 0.f, 0.f};
#pragma unroll
    for (int it = 0; it < 4; ++it)
        if (!aval[it]) {
            *reinterpret_cast<float4*>(Af + asmo[it])        = z4;
            *reinterpret_cast<float4*>(Af + K1A + asmo[it])  = z4;
        }
#pragma unroll
    for (int it = 0; it < 3; ++it)
        if (!bval[it]) {
            *reinterpret_cast<float4*>(Bf + bsmo[it])        = z4;
            *reinterpret_cast<float4*>(Bf + K1B + bsmo[it])  = z4;
        }

    const uint32_t Abase = s2u(Af);
    const uint32_t Bbase = s2u(Bf);

    float acc[2][6][4];
#pragma unroll
    for (int mt = 0; mt < 2; ++mt)
#pragma unroll
        for (int nt = 0; nt < 6; ++nt)
#pragma unroll
            for (int j = 0; j < 4; ++j) acc[mt][nt][j] = 0.f;

    // prologue: stage dc=0 into buffer 0
#pragma unroll
    for (int it = 0; it < 4; ++it) {
        if (aval[it]) cpa16(Abase + asmo[it] * 4, mi + aoff[it]);
        aoff[it] += 32u * K_;
    }
#pragma unroll
    for (int it = 0; it < 3; ++it) {
        if (bval[it]) cpa16(Bbase + bsmo[it] * 4, qi + boff[it]);
        boff[it] += 32u * Q_;
    }
    cpcommit();

#pragma unroll
    for (int dc = 0; dc < 4; ++dc) {
        if (dc < 3) {     // early-issue dc+1 into the other buffer
            const uint32_t sa = Abase + ((dc + 1) & 1) * (K1A * 4);
            const uint32_t sb = Bbase + ((dc + 1) & 1) * (K1B * 4);
#pragma unroll
            for (int it = 0; it < 4; ++it) {
                if (aval[it]) cpa16(sa + asmo[it] * 4, mi + aoff[it]);
                aoff[it] += 32u * K_;
            }
#pragma unroll
            for (int it = 0; it < 3; ++it) {
                if (bval[it]) cpa16(sb + bsmo[it] * 4, qi + boff[it]);
                boff[it] += 32u * Q_;
            }
            cpcommit();
            asm volatile("cp.async.wait_group 1;\n" ::: "memory");
        } else {
            asm volatile("cp.async.wait_group 0;\n" ::: "memory");
        }
        __syncthreads();

        const float* A  = Af + (dc & 1) * K1A;
        const float* Bv = Bf + (dc & 1) * K1B;

#pragma unroll
        for (int ks = 0; ks < 4; ++ks) {
            const int c = ks * 8 + tg;
            uint32_t af[2][4];
#pragma unroll
            for (int mt = 0; mt < 2; ++mt) {
                int r = wm * 32 + mt * 16 + g;
                af[mt][0] = f2tf(A[c * 136 + r]);
                af[mt][1] = f2tf(A[c * 136 + r + 8]);
                af[mt][2] = f2tf(A[(c + 4) * 136 + r]);
                af[mt][3] = f2tf(A[(c + 4) * 136 + r + 8]);
            }
#pragma unroll
            for (int nt = 0; nt < 6; ++nt) {
                int n = wn * 48 + nt * 8 + g;
                uint32_t bf[2] = { f2tf(Bv[c * 104 + n]), f2tf(Bv[(c + 4) * 104 + n]) };
                mma8(acc[0][nt], af[0], bf);
                mma8(acc[1][nt], af[1], bf);
            }
        }
        __syncthreads();
    }

    // exp + masked column sums
    float ls[6][2];
#pragma unroll
    for (int nt = 0; nt < 6; ++nt) { ls[nt][0] = 0.f; ls[nt][1] = 0.f; }

#pragma unroll
    for (int mt = 0; mt < 2; ++mt)
#pragma unroll
        for (int nt = 0; nt < 6; ++nt)
#pragma unroll
            for (int j = 0; j < 4; ++j) {
                int r  = wm * 32 + mt * 16 + ((j & 2) ? (g + 8) : g);
                int kg = k0 + r;
                float e = (kg < K_) ? __expf(acc[mt][nt][j] * SCALE) : 0.f;
                acc[mt][nt][j] = e;
                ls[nt][j & 1] += e;
            }

#pragma unroll
    for (int nt = 0; nt < 6; ++nt)
#pragma unroll
        for (int p = 0; p < 2; ++p) {
            float v = ls[nt][p];
            v += __shfl_xor_sync(0xffffffffu, v, 4);
            v += __shfl_xor_sync(0xffffffffu, v, 8);
            v += __shfl_xor_sync(0xffffffffu, v, 16);
            if (g == 0) cs[wm * 96 + wn * 48 + nt * 8 + tg * 2 + p] = v;
        }
    __syncthreads();

    if (tid < 96) {
        float s = cs[tid] + cs[96 + tid] + cs[192 + tid] + cs[288 + tid];
        g_part[((size_t)b * NKT + kt) * QPAD + qt * QT + tid] = s;
    }

    // stage e through smem; g_e stores vectorized (float4; tails 4-aligned)
    float* stg = Af;   // 32 x (stride 100) = 3200 <= K1A
#pragma unroll 1
    for (int chunk = 0; chunk < 4; ++chunk) {
        __syncthreads();
        if (wm == chunk) {
#pragma unroll
            for (int mt = 0; mt < 2; ++mt)
#pragma unroll
                for (int nt = 0; nt < 6; ++nt)
#pragma unroll
                    for (int j = 0; j < 4; ++j) {
                        int r = mt * 16 + ((j & 2) ? (g + 8) : g);
                        int c = wn * 48 + nt * 8 + tg * 2 + (j & 1);
                        stg[r * 100 + c] = __uint_as_float(f2tf(acc[mt][nt][j]));
                    }
        }
        __syncthreads();
#pragma unroll
        for (int it = 0; it < 3; ++it) {
            int i = tid + it * 256;              // 32 rows x 24 float4 = 768
            int r = i / 24, j = i - r * 24;
            int kg = k0 + chunk * 32 + r;
            int qg = q0 + j * 4;
            if (kg < K_ && qg < Q_) {            // widths 96/84 are 4-aligned
                float4 v = *reinterpret_cast<const float4*>(stg + r * 100 + j * 4);
                *reinterpret_cast<float4*>(
                    g_e + ((size_t)b * K_ + kg) * Q_ + qg) = v;
            }
        }
    }
}

// ===========================================================================
// K2: g_inv[b,q] = 1 / (exp(const) + sum_kt g_part)
// ===========================================================================
__global__ void k2_inv(const float* __restrict__ cst)
{
    int t = blockIdx.x * blockDim.x + threadIdx.x;
    if (t >= B_ * QPAD) return;
    int b  = t / QPAD;
    int qp = t - b * QPAD;
    float d = expf(cst[0]);
    const float* gp = g_part + (size_t)b * NKT * QPAD + qp;
#pragma unroll 4
    for (int kt = 0; kt < NKT; ++kt) d += gp[(size_t)kt * QPAD];
    g_inv[t] = 1.f / d;
}

// ===========================================================================
// K3: U = m_out @ g_e via 2-stage cp.async pipeline (R10-proven control
// flow). NEW: reads RAW m_out; cvt.rna applied on the 32 A-fragment loads
// per warp-iter (bit-identical to the former K0 pre-round; fma pipe was
// 3.7% busy). B stays pre-rounded in g_e. K0 kernel deleted.
// mem = U*inv[q] in epilogue; p = g_e*inv from smem B tile (1/4 duty cycle).
// Block tile M=128(d_o) x N=96(q); 405 k-chunks of 32 (exact).
// ===========================================================================
constexpr int ASTR  = 128 * 36;   // floats per A buffer (stride 36: conflict-free)
constexpr int BSTR  = 32 * 104;   // floats per B buffer (stride 104: conflict-free)
constexpr int SMEMF = 2 * ASTR + 2 * BSTR + 96;   // 15968 floats = 63872 B

__global__ __launch_bounds__(256, 2)
void k3_out(const float* __restrict__ m_out,
            float* __restrict__ out_mem, float* __restrict__ out_p)
{
    extern __shared__ float sm[];
    float* Ab   = sm;
    float* Bb   = sm + 2 * ASTR;
    float* sinv = sm + 2 * ASTR + 2 * BSTR;

    const int tid  = threadIdx.x;
    const int wid  = tid >> 5;
    const int lane = tid & 31;
    const int g    = lane >> 2;
    const int tg   = lane & 3;
    const int wm   = wid & 3;
    const int wn   = wid >> 2;

    const int dot = blockIdx.x;   // 0..3
    const int qt  = blockIdx.y;   // 0..16
    const int b   = blockIdx.z;
    const int q0  = qt * QT;
    const int do0 = dot * 128;

    if (tid < 96) sinv[tid] = g_inv[(size_t)b * QPAD + q0 + tid];

    const float* asrc[4]; uint32_t aoff[4];
#pragma unroll
    for (int it = 0; it < 4; ++it) {
        int i = tid + it * 256;          // A: 128 rows x 32 floats = 1024 x 16B
        int row = i >> 3;
        int kc4 = (i & 7) * 4;
        asrc[it] = m_out + ((size_t)b * DO + do0 + row) * K_ + kc4;
        aoff[it] = (uint32_t)((row * 36 + kc4) * 4);
    }
    const float* bsrc[3]; uint32_t boff[3]; int bkk[3], bqc[3];
#pragma unroll
    for (int it = 0; it < 3; ++it) {
        int i  = tid + it * 256;         // B: 32 rows x 96 floats = 768 x 16B
        int kk = i / 24;
        int qc = (i - kk * 24) * 4;
        bkk[it] = kk; bqc[it] = qc;
        bsrc[it] = g_e + (size_t)b * K_ * Q_ + (size_t)kk * Q_ + q0 + qc;
        boff[it] = (uint32_t)((kk * 104 + qc) * 4);
    }
    const uint32_t Abase = s2u(Ab);
    const uint32_t Bbase = s2u(Bb);

    float acc[2][6][4];
#pragma unroll
    for (int mt = 0; mt < 2; ++mt)
#pragma unroll
        for (int nt = 0; nt < 6; ++nt)
#pragma unroll
            for (int j = 0; j < 4; ++j) acc[mt][nt][j] = 0.f;

    // prologue: stage kc=0 into buffer 0
#pragma unroll
    for (int it = 0; it < 4; ++it) cpa16(Abase + aoff[it], asrc[it]);
#pragma unroll
    for (int it = 0; it < 3; ++it) cpa16(Bbase + boff[it], bsrc[it]);
    cpcommit();
#pragma unroll
    for (int it = 0; it < 4; ++it) asrc[it] += 32;
#pragma unroll
    for (int it = 0; it < 3; ++it) bsrc[it] += (size_t)32 * Q_;

    float* pout = out_p + (size_t)b * K_ * Q_;

#pragma unroll 1
    for (int kc = 0; kc < 405; ++kc) {
        if (kc < 404) {
            const uint32_t sa = Abase + ((kc + 1) & 1) * (ASTR * 4);
            const uint32_t sb = Bbase + ((kc + 1) & 1) * (BSTR * 4);
#pragma unroll
            for (int it = 0; it < 4; ++it) { cpa16(sa + aoff[it], asrc[it]); asrc[it] += 32; }
#pragma unroll
            for (int it = 0; it < 3; ++it) { cpa16(sb + boff[it], bsrc[it]); bsrc[it] += (size_t)32 * Q_; }
            cpcommit();
            asm volatile("cp.async.wait_group 1;\n" ::: "memory");
        } else {
            asm volatile("cp.async.wait_group 0;\n" ::: "memory");
        }
        __syncthreads();

        const float* A  = Ab + (kc & 1) * ASTR;
        const float* Bv = Bb + (kc & 1) * BSTR;

#pragma unroll
        for (int ks = 0; ks < 4; ++ks) {
            const int c = ks * 8 + tg;
            uint32_t af[2][4];
#pragma unroll
            for (int mt = 0; mt < 2; ++mt) {
                int r = wm * 32 + mt * 16 + g;
                af[mt][0] = f2tf(A[r * 36 + c]);
                af[mt][1] = f2tf(A[(r + 8) * 36 + c]);
                af[mt][2] = f2tf(A[r * 36 + c + 4]);
                af[mt][3] = f2tf(A[(r + 8) * 36 + c + 4]);
            }
#pragma unroll
            for (int nt = 0; nt < 6; ++nt) {
                int n = wn * 48 + nt * 8 + g;
                uint32_t bf[2] = { __float_as_uint(Bv[c * 104 + n]),
                                   __float_as_uint(Bv[(c + 4) * 104 + n]) };
                mma8(acc[0][nt], af[0], bf);
                mma8(acc[1][nt], af[1], bf);
            }
        }

        // p output: normalized e, from the smem tile (1/4 duty cycle)
        if ((kc & 3) == dot) {
            const int k0 = kc * 32;
#pragma unroll
            for (int it = 0; it < 3; ++it) {
                const int kk = bkk[it], qc = bqc[it];
                float4 v = *reinterpret_cast<const float4*>(Bv + kk * 104 + qc);
                float4 w;
                w.x = v.x * sinv[qc];
                w.y = v.y * sinv[qc + 1];
                w.z = v.z * sinv[qc + 2];
                w.w = v.w * sinv[qc + 3];
                const int qg = q0 + qc;
                float* dst = pout + (size_t)(k0 + kk) * Q_ + qg;
                if (qg + 3 < Q_) {
                    *reinterpret_cast<float4*>(dst) = w;
                } else {
                    if (qg     < Q_) dst[0] = w.x;
                    if (qg + 1 < Q_) dst[1] = w.y;
                    if (qg + 2 < Q_) dst[2] = w.z;
                    if (qg + 3 < Q_) dst[3] = w.w;
                }
            }
        }
        __syncthreads();
    }

    // epilogue: mem = U * inv[q]
#pragma unroll
    for (int mt = 0; mt < 2; ++mt)
#pragma unroll
        for (int nt = 0; nt < 6; ++nt)
#pragma unroll
            for (int j = 0; j < 4; ++j) {
                int r  = wm * 32 + mt * 16 + ((j & 2) ? (g + 8) : g);
                int cq = wn * 48 + nt * 8 + tg * 2 + (j & 1);
                int qg = q0 + cq;
                if (qg < Q_)
                    out_mem[((size_t)b * DO + do0 + r) * Q_ + qg] =
                        acc[mt][nt][j] * sinv[cq];
            }
}

extern "C" void kernel_launch(void* const* d_in, const int* in_sizes, int n_in,
                              void* d_out, int out_size) {
    const float* m_in  = (const float*)d_in[0];
    const float* m_out = (const float*)d_in[1];
    const float* q_in  = (const float*)d_in[2];
    const float* cst   = (const float*)d_in[3];
    float* out = (float*)d_out;

    cudaFuncSetAttribute(k1_scores, cudaFuncAttributeMaxDynamicSharedMemorySize,
                         K1SMEMF * 4);
    cudaFuncSetAttribute(k3_out, cudaFuncAttributeMaxDynamicSharedMemorySize,
                         SMEMF * 4);

    k1_scores<<<dim3(NKT, NQT, B_), 256, K1SMEMF * 4>>>(m_in, q_in);
    k2_inv<<<(B_ * QPAD + 255) / 256, 256>>>(cst);
    k3_out<<<dim3(4, NQT, B_), 256, SMEMF * 4>>>(m_out, out, out + MEM_ELEMS);
}